// round 2
// baseline (speedup 1.0000x reference)
#include <cuda_runtime.h>
#include <math.h>

// Problem shapes (fixed by the dataset)
#define B_ 1024
#define S_ 64
#define D_ 512
#define R_ 16
#define C_ 1000

// Scratch (device globals: allocation-free per harness rules)
__device__ float g_lrcov[(size_t)B_ * D_ * R_];   // [b][d*R + r]
__device__ float g_diag [(size_t)B_ * D_];        // [b][d]
__device__ float g_X    [(size_t)B_ * S_ * D_];   // [(b*S+s)][d]  pre_logits

// ----------------------------------------------------------------------------
// Tiled SGEMM:  Cmat[m,n] = sum_k A[m,k] * Bt[n,k]   (A: MxK, Bt: NxK row-major)
// MODE 0: write g_lrcov,  epilogue: x + bias[n]
// MODE 1: write g_diag,   epilogue: softplus(x + bias[n]) + 1e-3
// MODE 2: read A from g_X, write Cout, epilogue: (x + bias[n]) * (1/1.5)
// Tiles: 128x128x16, 256 threads, 8x8 per-thread micro-tile.
// M must be a multiple of 128 and K a multiple of 16 (true for all calls);
// N edge is guarded (N=1000 case).
// ----------------------------------------------------------------------------
template <int MODE>
__global__ void __launch_bounds__(256, 2)
gemm_tn(const float* __restrict__ A_in,
        const float* __restrict__ Bt,
        const float* __restrict__ bias,
        float* __restrict__ Cout,
        int M, int N, int K)
{
    __shared__ float As[16][132];  // [k][m], pad to keep 16B align + avoid conflicts
    __shared__ float Bs[16][132];  // [k][n]

    const float* A = (MODE == 2) ? g_X : A_in;
    float* Cmat = (MODE == 0) ? g_lrcov : (MODE == 1) ? g_diag : Cout;

    const int m0 = blockIdx.y * 128;
    const int n0 = blockIdx.x * 128;
    const int tid = threadIdx.x;
    const int tx = tid & 15;        // 16 cols of threads -> n
    const int ty = tid >> 4;        // 16 rows of threads -> m

    float acc[8][8];
#pragma unroll
    for (int i = 0; i < 8; i++)
#pragma unroll
        for (int j = 0; j < 8; j++) acc[i][j] = 0.0f;

    for (int k0 = 0; k0 < K; k0 += 16) {
        // Load A tile (128 x 16) transposed into As[k][m]
#pragma unroll
        for (int q = 0; q < 2; q++) {
            int f4  = tid * 2 + q;          // 0..511
            int row = f4 >> 2;              // 0..127
            int kq  = (f4 & 3) * 4;         // 0,4,8,12
            float4 v = *(const float4*)&A[(size_t)(m0 + row) * K + k0 + kq];
            As[kq + 0][row] = v.x;
            As[kq + 1][row] = v.y;
            As[kq + 2][row] = v.z;
            As[kq + 3][row] = v.w;
        }
        // Load B tile (128 x 16) transposed into Bs[k][n], guard N edge
#pragma unroll
        for (int q = 0; q < 2; q++) {
            int f4  = tid * 2 + q;
            int row = f4 >> 2;
            int kq  = (f4 & 3) * 4;
            float4 v = make_float4(0.f, 0.f, 0.f, 0.f);
            if (n0 + row < N)
                v = *(const float4*)&Bt[(size_t)(n0 + row) * K + k0 + kq];
            Bs[kq + 0][row] = v.x;
            Bs[kq + 1][row] = v.y;
            Bs[kq + 2][row] = v.z;
            Bs[kq + 3][row] = v.w;
        }
        __syncthreads();

#pragma unroll
        for (int kk = 0; kk < 16; kk++) {
            float4 a0 = *(const float4*)&As[kk][ty * 8];
            float4 a1 = *(const float4*)&As[kk][ty * 8 + 4];
            float4 b0 = *(const float4*)&Bs[kk][tx * 8];
            float4 b1 = *(const float4*)&Bs[kk][tx * 8 + 4];
            float a[8] = {a0.x, a0.y, a0.z, a0.w, a1.x, a1.y, a1.z, a1.w};
            float b[8] = {b0.x, b0.y, b0.z, b0.w, b1.x, b1.y, b1.z, b1.w};
#pragma unroll
            for (int i = 0; i < 8; i++)
#pragma unroll
                for (int j = 0; j < 8; j++)
                    acc[i][j] = fmaf(a[i], b[j], acc[i][j]);
        }
        __syncthreads();
    }

    // Epilogue
#pragma unroll
    for (int i = 0; i < 8; i++) {
        int m = m0 + ty * 8 + i;
#pragma unroll
        for (int j = 0; j < 8; j++) {
            int n = n0 + tx * 8 + j;
            if (n < N) {
                float x = acc[i][j] + __ldg(&bias[n]);
                if (MODE == 1) {
                    // stable softplus = max(x,0) + log1p(exp(-|x|)), then + min_scale
                    x = fmaxf(x, 0.0f) + log1pf(expf(-fabsf(x)));
                    x += 1e-3f;
                } else if (MODE == 2) {
                    x *= (1.0f / 1.5f);
                }
                Cmat[(size_t)m * N + n] = x;
            }
        }
    }
}

// ----------------------------------------------------------------------------
// gen_x: X[b,s,d] = features[b,d] + sum_r lrcov[b,d,r]*noise_lr[b,s,r]
//                 + diag_std[b,d]*noise_diag[b,s,d]
// Block handles (b, d-chunk of 64) x all 64 s. lrcov & noise_lr staged in smem.
// ----------------------------------------------------------------------------
__global__ void __launch_bounds__(256)
gen_x(const float* __restrict__ feat,
      const float* __restrict__ nlr,
      const float* __restrict__ nd)
{
    __shared__ float s_lr [64][17];   // [d_local][r]
    __shared__ float s_nlr[64][17];   // [s][r]
    __shared__ float s_feat[64];
    __shared__ float s_diag[64];

    const int b  = blockIdx.y;
    const int d0 = blockIdx.x * 64;
    const int tid = threadIdx.x;

    {
        int dl = tid >> 2;              // 0..63
        int rq = (tid & 3) * 4;         // 0,4,8,12
        float4 v = *(const float4*)&g_lrcov[((size_t)b * D_ + d0 + dl) * R_ + rq];
        s_lr[dl][rq + 0] = v.x; s_lr[dl][rq + 1] = v.y;
        s_lr[dl][rq + 2] = v.z; s_lr[dl][rq + 3] = v.w;
        float4 w = *(const float4*)&nlr[((size_t)b * S_ + dl) * R_ + rq];
        s_nlr[dl][rq + 0] = w.x; s_nlr[dl][rq + 1] = w.y;
        s_nlr[dl][rq + 2] = w.z; s_nlr[dl][rq + 3] = w.w;
    }
    if (tid < 64) {
        s_feat[tid] = feat[(size_t)b * D_ + d0 + tid];
        s_diag[tid] = g_diag[(size_t)b * D_ + d0 + tid];
    }
    __syncthreads();

    for (int e = tid; e < 64 * 64; e += 256) {
        int ss = e >> 6;       // s
        int dl = e & 63;       // d local
        float acc = s_feat[dl];
#pragma unroll
        for (int r = 0; r < 16; r++)
            acc = fmaf(s_lr[dl][r], s_nlr[ss][r], acc);
        size_t idx = ((size_t)b * S_ + ss) * D_ + d0 + dl;
        acc = fmaf(s_diag[dl], nd[idx], acc);
        g_X[idx] = acc;
    }
}

extern "C" void kernel_launch(void* const* d_in, const int* in_sizes, int n_in,
                              void* d_out, int out_size)
{
    const float* features   = (const float*)d_in[0];  // (1024, 512)
    const float* W_cov      = (const float*)d_in[1];  // (8192, 512)
    const float* b_cov      = (const float*)d_in[2];  // (8192,)
    const float* W_diag     = (const float*)d_in[3];  // (512, 512)
    const float* b_diag     = (const float*)d_in[4];  // (512,)
    const float* W_cls      = (const float*)d_in[5];  // (1000, 512)
    const float* b_cls      = (const float*)d_in[6];  // (1000,)
    const float* noise_diag = (const float*)d_in[7];  // (1024, 64, 512)
    const float* noise_lr   = (const float*)d_in[8];  // (1024, 64, 16)
    float* out = (float*)d_out;                       // (1024, 64, 1000)

    // 1) lrcov = features @ W_cov^T + b_cov      (M=1024, N=8192, K=512)
    gemm_tn<0><<<dim3(8192 / 128, 1024 / 128), 256>>>(
        features, W_cov, b_cov, nullptr, 1024, 8192, 512);

    // 2) diag_std = softplus(features @ W_diag^T + b_diag) + 1e-3  (N=512)
    gemm_tn<1><<<dim3(512 / 128, 1024 / 128), 256>>>(
        features, W_diag, b_diag, nullptr, 1024, 512, 512);

    // 3) pre_logits into g_X
    gen_x<<<dim3(D_ / 64, B_), 256>>>(features, noise_lr, noise_diag);

    // 4) out = (g_X @ W_cls^T + b_cls) / 1.5     (M=65536, N=1000, K=512)
    gemm_tn<2><<<dim3((1000 + 127) / 128, 65536 / 128), 256>>>(
        nullptr, W_cls, b_cls, out, 65536, 1000, 512);
}

// round 5
// speedup vs baseline: 2.1418x; 2.1418x over previous
#include <cuda_runtime.h>
#include <cuda_bf16.h>
#include <cstdint>
#include <math.h>

#define B_ 1024
#define S_ 64
#define D_ 512
#define R_ 16
#define C_ 1000
#define M4 (B_ * S_)          // 65536
#define NPAD 1024             // padded C rows for GEMM4 B operand
#define NK 32                 // K/16

// ---------------- device scratch (allocation-free) ----------------
__device__ float g_lrcov[(size_t)B_ * D_ * R_];
__device__ float g_diag [(size_t)B_ * D_];
__device__ __nv_bfloat16 g_Xh[(size_t)M4 * D_];
__device__ __nv_bfloat16 g_Xl[(size_t)M4 * D_];
__device__ __nv_bfloat16 g_Fh[(size_t)B_ * D_];
__device__ __nv_bfloat16 g_Fl[(size_t)B_ * D_];
__device__ __nv_bfloat16 g_Wcovh[(size_t)(D_*R_) * D_];
__device__ __nv_bfloat16 g_Wcovl[(size_t)(D_*R_) * D_];
__device__ __nv_bfloat16 g_Wch[(size_t)NPAD * D_];
__device__ __nv_bfloat16 g_Wcl[(size_t)NPAD * D_];

// ---------------- async-copy helpers (sm_80 baseline features) ----------------
__device__ __forceinline__ uint32_t smem_u32(const void* p) {
    uint32_t a;
    asm("{ .reg .u64 t; cvta.to.shared.u64 t, %1; cvt.u32.u64 %0, t; }" : "=r"(a) : "l"(p));
    return a;
}
#define CP16(sa, ga)  asm volatile("cp.async.cg.shared.global [%0], [%1], 16;" :: "r"(sa), "l"(ga))
#define CP_COMMIT()   asm volatile("cp.async.commit_group;" ::: "memory")
#define CP_WAIT2()    asm volatile("cp.async.wait_group 2;" ::: "memory")
#define CP_WAIT0()    asm volatile("cp.async.wait_group 0;" ::: "memory")

// mma.sync m16n8k16 bf16 -> f32 accum (sm_80 feature, compiles for plain sm_103)
__device__ __forceinline__ void mma16816(float* c, const uint32_t* a, const uint32_t* b) {
    asm volatile(
        "mma.sync.aligned.m16n8k16.row.col.f32.bf16.bf16.f32 "
        "{%0,%1,%2,%3}, {%4,%5,%6,%7}, {%8,%9}, {%0,%1,%2,%3};"
        : "+f"(c[0]), "+f"(c[1]), "+f"(c[2]), "+f"(c[3])
        : "r"(a[0]), "r"(a[1]), "r"(a[2]), "r"(a[3]), "r"(b[0]), "r"(b[1]));
}

// ---------------- smem layout for mma_gemm ----------------
// Per stage: Ah | Al | Bh | Bl, each 128 rows x 48 bytes (16 bf16 + 8 pad)
// 48B row stride = 12 banks: fragment reads (banks (12r+q) mod 32) are conflict-free.
#define MAT_BYTES  (128 * 48)          // 6144
#define STG_BYTES  (4 * MAT_BYTES)     // 24576
#define SMEM_MM    (3 * STG_BYTES)     // 73728, 3-stage pipeline

__device__ __forceinline__ void frag_a(uint32_t a[4][4], const char* p, int wm, int qr, int qc) {
#pragma unroll
    for (int i = 0; i < 4; i++) {
        const char* base = p + (wm * 64 + i * 16 + qr) * 48 + qc * 4;
        a[i][0] = *(const uint32_t*)(base);          // (r,   k)
        a[i][1] = *(const uint32_t*)(base + 384);    // (r+8, k)
        a[i][2] = *(const uint32_t*)(base + 16);     // (r,   k+8)
        a[i][3] = *(const uint32_t*)(base + 400);    // (r+8, k+8)
    }
}
__device__ __forceinline__ void frag_b(uint32_t b[4][2], const char* p, int wn, int qr, int qc) {
#pragma unroll
    for (int j = 0; j < 4; j++) {
        const char* base = p + (wn * 32 + j * 8 + qr) * 48 + qc * 4;
        b[j][0] = *(const uint32_t*)(base);          // (k,   n)
        b[j][1] = *(const uint32_t*)(base + 16);     // (k+8, n)
    }
}

// ----------------------------------------------------------------------------
// Split-bf16 tensor-core GEMM (3-term: hh + hl + lh), K=512 fixed.
// C[m,n] = (sum_k (Ah+Al)[m,k]*(Bh+Bl)[n,k] + bias[n]) * scale
// CTA tile 128x128, 8 warps (2x4), warp tile 64x32, cp.async 3-stage pipeline.
// M % 128 == 0; operand N % 128 == 0 (B zero-padded); stores guarded to nValid.
// ----------------------------------------------------------------------------
__global__ void __launch_bounds__(256, 1)
mma_gemm(const __nv_bfloat16* __restrict__ Ah, const __nv_bfloat16* __restrict__ Al,
         const __nv_bfloat16* __restrict__ Bh, const __nv_bfloat16* __restrict__ Bl,
         const float* __restrict__ bias, float* __restrict__ Cout,
         int Nout, int nValid, float scale)
{
    extern __shared__ char smem[];
    const uint32_t sbase = smem_u32(smem);
    const int tid = threadIdx.x, wid = tid >> 5, lane = tid & 31;
    const int wm = wid & 1, wn = wid >> 1;
    const int qr = lane >> 2, qc = lane & 3;
    const int m0 = blockIdx.y * 128, n0 = blockIdx.x * 128;

    // per-thread load slots: row = tid>>1, chunk = tid&1 (two 16B chunks per 32B row)
    const int lrow = tid >> 1, lch = tid & 1;
    const uint32_t s_off = (uint32_t)(lrow * 48 + lch * 16);
    const size_t gA = (size_t)(m0 + lrow) * 512 + lch * 8;   // + ks*16
    const size_t gB = (size_t)(n0 + lrow) * 512 + lch * 8;

    float acc[4][4][4];
#pragma unroll
    for (int i = 0; i < 4; i++)
#pragma unroll
        for (int j = 0; j < 4; j++)
#pragma unroll
            for (int r = 0; r < 4; r++) acc[i][j][r] = 0.0f;

#define ISSUE(ks) do {                                                        \
        uint32_t st = sbase + ((ks) % 3) * STG_BYTES + s_off;                 \
        size_t ko = (size_t)(ks) * 16;                                        \
        CP16(st,                     Ah + gA + ko);                           \
        CP16(st + MAT_BYTES,         Al + gA + ko);                           \
        CP16(st + 2 * MAT_BYTES,     Bh + gB + ko);                           \
        CP16(st + 3 * MAT_BYTES,     Bl + gB + ko);                           \
        CP_COMMIT();                                                          \
    } while (0)

    ISSUE(0);
    ISSUE(1);

    for (int ks = 0; ks < NK; ks++) {
        if (ks + 2 < NK) ISSUE(ks + 2);
        if (ks < NK - 2) CP_WAIT2(); else CP_WAIT0();
        __syncthreads();

        const char* sp  = smem + (ks % 3) * STG_BYTES;
        uint32_t ah[4][4], al[4][4], bh[4][2], bl[4][2];
        frag_a(ah, sp,                 wm, qr, qc);
        frag_b(bh, sp + 2 * MAT_BYTES, wn, qr, qc);
#pragma unroll
        for (int i = 0; i < 4; i++)
#pragma unroll
            for (int j = 0; j < 4; j++) mma16816(acc[i][j], ah[i], bh[j]);

        frag_b(bl, sp + 3 * MAT_BYTES, wn, qr, qc);
#pragma unroll
        for (int i = 0; i < 4; i++)
#pragma unroll
            for (int j = 0; j < 4; j++) mma16816(acc[i][j], ah[i], bl[j]);

        frag_a(al, sp + MAT_BYTES,     wm, qr, qc);
#pragma unroll
        for (int i = 0; i < 4; i++)
#pragma unroll
            for (int j = 0; j < 4; j++) mma16816(acc[i][j], al[i], bh[j]);

        __syncthreads();
    }
#undef ISSUE

    // epilogue: direct stores, float2 per fragment row (cols are even-aligned pairs)
#pragma unroll
    for (int i = 0; i < 4; i++) {
        int row = m0 + wm * 64 + i * 16 + qr;
#pragma unroll
        for (int j = 0; j < 4; j++) {
            int col = n0 + wn * 32 + j * 8 + qc * 2;
            if (col < nValid) {
                float bv0 = __ldg(&bias[col]), bv1 = __ldg(&bias[col + 1]);
                float2 v0 = make_float2((acc[i][j][0] + bv0) * scale,
                                        (acc[i][j][1] + bv1) * scale);
                float2 v1 = make_float2((acc[i][j][2] + bv0) * scale,
                                        (acc[i][j][3] + bv1) * scale);
                *(float2*)&Cout[(size_t)row * Nout + col]       = v0;
                *(float2*)&Cout[(size_t)(row + 8) * Nout + col] = v1;
            }
        }
    }
}

// ---------------- fp32 -> bf16 hi/lo split (with zero pad) ----------------
__global__ void __launch_bounds__(256)
split_bf16(const float* __restrict__ src, __nv_bfloat16* __restrict__ h,
           __nv_bfloat16* __restrict__ l, size_t n_src, size_t n_total)
{
    size_t i = (size_t)blockIdx.x * 256 + threadIdx.x;
    if (i >= n_total) return;
    float x = (i < n_src) ? src[i] : 0.0f;
    __nv_bfloat16 hi = __float2bfloat16(x);
    h[i] = hi;
    l[i] = __float2bfloat16(x - __bfloat162float(hi));
}

// ---------------- FFMA GEMM for diag (small: 0.5 GF) ----------------
__global__ void __launch_bounds__(256, 2)
gemm_diag(const float* __restrict__ A, const float* __restrict__ Bt,
          const float* __restrict__ bias, int M, int N, int K)
{
    __shared__ float As[16][132];
    __shared__ float Bs[16][132];
    const int m0 = blockIdx.y * 128, n0 = blockIdx.x * 128;
    const int tid = threadIdx.x, tx = tid & 15, ty = tid >> 4;
    float acc[8][8];
#pragma unroll
    for (int i = 0; i < 8; i++)
#pragma unroll
        for (int j = 0; j < 8; j++) acc[i][j] = 0.0f;

    for (int k0 = 0; k0 < K; k0 += 16) {
#pragma unroll
        for (int q = 0; q < 2; q++) {
            int f4 = tid * 2 + q, row = f4 >> 2, kq = (f4 & 3) * 4;
            float4 v = *(const float4*)&A[(size_t)(m0 + row) * K + k0 + kq];
            As[kq][row] = v.x; As[kq+1][row] = v.y; As[kq+2][row] = v.z; As[kq+3][row] = v.w;
            float4 w = *(const float4*)&Bt[(size_t)(n0 + row) * K + k0 + kq];
            Bs[kq][row] = w.x; Bs[kq+1][row] = w.y; Bs[kq+2][row] = w.z; Bs[kq+3][row] = w.w;
        }
        __syncthreads();
#pragma unroll
        for (int kk = 0; kk < 16; kk++) {
            float4 a0 = *(const float4*)&As[kk][ty*8], a1 = *(const float4*)&As[kk][ty*8+4];
            float4 b0 = *(const float4*)&Bs[kk][tx*8], b1 = *(const float4*)&Bs[kk][tx*8+4];
            float a[8] = {a0.x,a0.y,a0.z,a0.w,a1.x,a1.y,a1.z,a1.w};
            float b[8] = {b0.x,b0.y,b0.z,b0.w,b1.x,b1.y,b1.z,b1.w};
#pragma unroll
            for (int i = 0; i < 8; i++)
#pragma unroll
                for (int j = 0; j < 8; j++) acc[i][j] = fmaf(a[i], b[j], acc[i][j]);
        }
        __syncthreads();
    }
#pragma unroll
    for (int i = 0; i < 8; i++) {
        int m = m0 + ty * 8 + i;
#pragma unroll
        for (int j = 0; j < 8; j++) {
            int n = n0 + tx * 8 + j;
            float x = acc[i][j] + __ldg(&bias[n]);
            x = fmaxf(x, 0.0f) + log1pf(expf(-fabsf(x))) + 1e-3f;   // softplus + min_scale
            g_diag[(size_t)m * N + n] = x;
        }
    }
}

// ---------------- sample generation -> X (bf16 hi/lo) ----------------
__global__ void __launch_bounds__(256)
gen_x(const float* __restrict__ feat, const float* __restrict__ nlr,
      const float* __restrict__ nd)
{
    __shared__ float s_lr [64][17];
    __shared__ float s_nlr[64][17];
    __shared__ float s_feat[64];
    __shared__ float s_diag[64];
    const int b = blockIdx.y, d0 = blockIdx.x * 64, tid = threadIdx.x;
    {
        int dl = tid >> 2, rq = (tid & 3) * 4;
        float4 v = *(const float4*)&g_lrcov[((size_t)b * D_ + d0 + dl) * R_ + rq];
        s_lr[dl][rq] = v.x; s_lr[dl][rq+1] = v.y; s_lr[dl][rq+2] = v.z; s_lr[dl][rq+3] = v.w;
        float4 w = *(const float4*)&nlr[((size_t)b * S_ + dl) * R_ + rq];
        s_nlr[dl][rq] = w.x; s_nlr[dl][rq+1] = w.y; s_nlr[dl][rq+2] = w.z; s_nlr[dl][rq+3] = w.w;
    }
    if (tid < 64) {
        s_feat[tid] = feat[(size_t)b * D_ + d0 + tid];
        s_diag[tid] = g_diag[(size_t)b * D_ + d0 + tid];
    }
    __syncthreads();
    for (int e = tid; e < 64 * 64; e += 256) {
        int ss = e >> 6, dl = e & 63;
        float acc = s_feat[dl];
#pragma unroll
        for (int r = 0; r < 16; r++) acc = fmaf(s_lr[dl][r], s_nlr[ss][r], acc);
        size_t idx = ((size_t)b * S_ + ss) * D_ + d0 + dl;
        acc = fmaf(s_diag[dl], nd[idx], acc);
        __nv_bfloat16 hi = __float2bfloat16(acc);
        g_Xh[idx] = hi;
        g_Xl[idx] = __float2bfloat16(acc - __bfloat162float(hi));
    }
}

extern "C" void kernel_launch(void* const* d_in, const int* in_sizes, int n_in,
                              void* d_out, int out_size)
{
    const float* features   = (const float*)d_in[0];
    const float* W_cov      = (const float*)d_in[1];
    const float* b_cov      = (const float*)d_in[2];
    const float* W_diag     = (const float*)d_in[3];
    const float* b_diag     = (const float*)d_in[4];
    const float* W_cls      = (const float*)d_in[5];
    const float* b_cls      = (const float*)d_in[6];
    const float* noise_diag = (const float*)d_in[7];
    const float* noise_lr   = (const float*)d_in[8];
    float* out = (float*)d_out;

    cudaFuncSetAttribute(mma_gemm, cudaFuncAttributeMaxDynamicSharedMemorySize, SMEM_MM);

    __nv_bfloat16 *Fh, *Fl, *Wcovh, *Wcovl, *Wch, *Wcl, *Xh, *Xl;
    cudaGetSymbolAddress((void**)&Fh, g_Fh);       cudaGetSymbolAddress((void**)&Fl, g_Fl);
    cudaGetSymbolAddress((void**)&Wcovh, g_Wcovh); cudaGetSymbolAddress((void**)&Wcovl, g_Wcovl);
    cudaGetSymbolAddress((void**)&Wch, g_Wch);     cudaGetSymbolAddress((void**)&Wcl, g_Wcl);
    cudaGetSymbolAddress((void**)&Xh, g_Xh);       cudaGetSymbolAddress((void**)&Xl, g_Xl);
    float* lrcov; cudaGetSymbolAddress((void**)&lrcov, g_lrcov);

    // splits
    split_bf16<<<(B_*D_ + 255)/256, 256>>>(features, Fh, Fl, (size_t)B_*D_, (size_t)B_*D_);
    split_bf16<<<((size_t)D_*R_*D_ + 255)/256, 256>>>(W_cov, Wcovh, Wcovl,
                                                      (size_t)D_*R_*D_, (size_t)D_*R_*D_);
    split_bf16<<<((size_t)NPAD*D_ + 255)/256, 256>>>(W_cls, Wch, Wcl,
                                                     (size_t)C_*D_, (size_t)NPAD*D_);

    // 1) lrcov = features @ W_cov^T + b_cov   (M=1024, N=8192) on tensor pipe
    mma_gemm<<<dim3(8192/128, 1024/128), 256, SMEM_MM>>>(
        Fh, Fl, Wcovh, Wcovl, b_cov, lrcov, 8192, 8192, 1.0f);

    // 2) diag_std (small, FFMA)
    gemm_diag<<<dim3(512/128, 1024/128), 256>>>(features, W_diag, b_diag, 1024, 512, 512);

    // 3) pre_logits -> Xh/Xl
    gen_x<<<dim3(D_/64, B_), 256>>>(features, noise_lr, noise_diag);

    // 4) out = (X @ W_cls^T + b_cls) / 1.5  (M=65536, N=1000 padded to 1024) on tensor pipe
    mma_gemm<<<dim3(NPAD/128, M4/128), 256, SMEM_MM>>>(
        Xh, Xl, Wch, Wcl, b_cls, out, C_, C_, 1.0f/1.5f);
}

// round 7
// speedup vs baseline: 2.2833x; 1.0661x over previous
#include <cuda_runtime.h>
#include <cuda_bf16.h>
#include <cstdint>
#include <math.h>

#define B_ 1024
#define S_ 64
#define D_ 512
#define R_ 16
#define C_ 1000
#define M4 (B_ * S_)          // 65536
#define NPAD 1024             // padded C rows for GEMM4 B operand
#define NK 32                 // K/16

// ---------------- device scratch (allocation-free) ----------------
__device__ float g_lrcov[(size_t)B_ * D_ * R_];
__device__ float g_diag [(size_t)B_ * D_];
__device__ __nv_bfloat16 g_Xh[(size_t)M4 * D_];
__device__ __nv_bfloat16 g_Xl[(size_t)M4 * D_];
__device__ __nv_bfloat16 g_Fh[(size_t)B_ * D_];
__device__ __nv_bfloat16 g_Fl[(size_t)B_ * D_];
__device__ __nv_bfloat16 g_Wcovh[(size_t)(D_*R_) * D_];
__device__ __nv_bfloat16 g_Wcovl[(size_t)(D_*R_) * D_];
__device__ __nv_bfloat16 g_Wch[(size_t)NPAD * D_];
__device__ __nv_bfloat16 g_Wcl[(size_t)NPAD * D_];

// ---------------- helpers ----------------
__device__ __forceinline__ uint32_t smem_u32(const void* p) {
    uint32_t a;
    asm("{ .reg .u64 t; cvta.to.shared.u64 t, %1; cvt.u32.u64 %0, t; }" : "=r"(a) : "l"(p));
    return a;
}
#define CP16(sa, ga)  asm volatile("cp.async.cg.shared.global [%0], [%1], 16;" :: "r"(sa), "l"(ga))
#define CP_COMMIT()   asm volatile("cp.async.commit_group;" ::: "memory")
#define CP_WAITG(n)   asm volatile("cp.async.wait_group %0;" :: "n"(n) : "memory")

__device__ __forceinline__ void mma16816(float* c, const uint32_t* a, const uint32_t* b) {
    asm volatile(
        "mma.sync.aligned.m16n8k16.row.col.f32.bf16.bf16.f32 "
        "{%0,%1,%2,%3}, {%4,%5,%6,%7}, {%8,%9}, {%0,%1,%2,%3};"
        : "+f"(c[0]), "+f"(c[1]), "+f"(c[2]), "+f"(c[3])
        : "r"(a[0]), "r"(a[1]), "r"(a[2]), "r"(a[3]), "r"(b[0]), "r"(b[1]));
}
__device__ __forceinline__ void ldm_x4(uint32_t* r, uint32_t addr) {
    asm volatile("ldmatrix.sync.aligned.m8n8.x4.shared.b16 {%0,%1,%2,%3}, [%4];"
        : "=r"(r[0]), "=r"(r[1]), "=r"(r[2]), "=r"(r[3]) : "r"(addr));
}

// ---------------- smem layout ----------------
// Per stage: Ah | Al | Bh | Bl, each 128 rows x 48B (16 bf16 + 16B pad).
// 48B stride = 12 banks: both ldmatrix phases and fragment reads conflict-free.
#define MAT_BYTES  (128 * 48)          // 6144
#define STG_BYTES  (4 * MAT_BYTES)     // 24576
#define NSTG 4
#define SMEM_MM    (NSTG * STG_BYTES)  // 98304

// ----------------------------------------------------------------------------
// Split-bf16 tensor-core GEMM (3 terms: hh + hl + lh), K=512 fixed.
// C[m,n] = (sum_k (Ah+Al)[m,k]*(Bh+Bl)[n,k] + bias[n]) * scale
// CTA 128x128, 8 warps (2x4), warp 64x32, cp.async 4-stage, ldmatrix fragments,
// one __syncthreads per k-step (prefetch issued post-barrier => no WAR race).
// ----------------------------------------------------------------------------
__global__ void __launch_bounds__(256, 2)
mma_gemm(const __nv_bfloat16* __restrict__ Ah, const __nv_bfloat16* __restrict__ Al,
         const __nv_bfloat16* __restrict__ Bh, const __nv_bfloat16* __restrict__ Bl,
         const float* __restrict__ bias, float* __restrict__ Cout,
         int Nout, int nValid, float scale)
{
    extern __shared__ char smem[];
    const uint32_t sbase = smem_u32(smem);
    const int tid = threadIdx.x, wid = tid >> 5, lane = tid & 31;
    const int wm = wid & 1, wn = wid >> 1;
    const int qr = lane >> 2, qc = lane & 3;
    const int m0 = blockIdx.y * 128, n0 = blockIdx.x * 128;

    // cp.async slots: row = tid>>1 (0..127), chunk = tid&1
    const int lrow = tid >> 1, lch = tid & 1;
    const uint32_t s_off = (uint32_t)(lrow * 48 + lch * 16);
    const size_t gA = (size_t)(m0 + lrow) * 512 + lch * 8;
    const size_t gB = (size_t)(n0 + lrow) * 512 + lch * 8;

    // ldmatrix per-lane row offsets (within one 128x48 matrix)
    const uint32_t aoff = (uint32_t)((wm * 64 + (lane & 15)) * 48 + (lane >> 4) * 16);
    const uint32_t boff = (uint32_t)((wn * 32 + (lane & 7) + ((lane & 16) >> 1)) * 48
                                     + ((lane >> 3) & 1) * 16);

    float acc[4][4][4];
#pragma unroll
    for (int i = 0; i < 4; i++)
#pragma unroll
        for (int j = 0; j < 4; j++)
#pragma unroll
            for (int r = 0; r < 4; r++) acc[i][j][r] = 0.0f;

#define ISSUE(ks) do {                                                        \
        uint32_t st = sbase + ((ks) & (NSTG - 1)) * STG_BYTES + s_off;        \
        size_t ko = (size_t)(ks) * 16;                                        \
        CP16(st,                 Ah + gA + ko);                               \
        CP16(st + MAT_BYTES,     Al + gA + ko);                               \
        CP16(st + 2 * MAT_BYTES, Bh + gB + ko);                               \
        CP16(st + 3 * MAT_BYTES, Bl + gB + ko);                               \
        CP_COMMIT();                                                          \
    } while (0)

    ISSUE(0); ISSUE(1); ISSUE(2);

    for (int ks = 0; ks < NK; ks++) {
        // stage ks%4 ready when ≤(issued - (ks+1)) groups pending
        if (ks + 3 <= NK)      CP_WAITG(2);
        else if (ks + 2 == NK) CP_WAITG(1);
        else                   CP_WAITG(0);
        __syncthreads();                  // publishes stage ks; all warps done with stage ks-1
        if (ks + 3 < NK) ISSUE(ks + 3);   // safe: overwrites stage ks-1 after barrier

        const uint32_t stg = sbase + (ks & (NSTG - 1)) * STG_BYTES;
        uint32_t a[4][4], bh[4][2], bl[4][2];

        ldm_x4(&bh[0][0], stg + 2 * MAT_BYTES + boff);
        ldm_x4(&bh[2][0], stg + 2 * MAT_BYTES + boff + 768);
        ldm_x4(&bl[0][0], stg + 3 * MAT_BYTES + boff);
        ldm_x4(&bl[2][0], stg + 3 * MAT_BYTES + boff + 768);
#pragma unroll
        for (int i = 0; i < 4; i++) ldm_x4(&a[i][0], stg + aoff + i * 768);

#pragma unroll
        for (int i = 0; i < 4; i++)
#pragma unroll
            for (int j = 0; j < 4; j++) mma16816(acc[i][j], a[i], bh[j]);
#pragma unroll
        for (int i = 0; i < 4; i++)
#pragma unroll
            for (int j = 0; j < 4; j++) mma16816(acc[i][j], a[i], bl[j]);

#pragma unroll
        for (int i = 0; i < 4; i++) ldm_x4(&a[i][0], stg + MAT_BYTES + aoff + i * 768);
#pragma unroll
        for (int i = 0; i < 4; i++)
#pragma unroll
            for (int j = 0; j < 4; j++) mma16816(acc[i][j], a[i], bh[j]);
    }
#undef ISSUE

    // epilogue: direct float2 stores (fragment cols are even-aligned pairs)
#pragma unroll
    for (int i = 0; i < 4; i++) {
        int row = m0 + wm * 64 + i * 16 + qr;
#pragma unroll
        for (int j = 0; j < 4; j++) {
            int col = n0 + wn * 32 + j * 8 + qc * 2;
            if (col < nValid) {
                float bv0 = __ldg(&bias[col]), bv1 = __ldg(&bias[col + 1]);
                float2 v0 = make_float2((acc[i][j][0] + bv0) * scale,
                                        (acc[i][j][1] + bv1) * scale);
                float2 v1 = make_float2((acc[i][j][2] + bv0) * scale,
                                        (acc[i][j][3] + bv1) * scale);
                *(float2*)&Cout[(size_t)row * Nout + col]       = v0;
                *(float2*)&Cout[(size_t)(row + 8) * Nout + col] = v1;
            }
        }
    }
}

// ---------------- fp32 -> bf16 hi/lo split (with zero pad) ----------------
__global__ void __launch_bounds__(256)
split_bf16(const float* __restrict__ src, __nv_bfloat16* __restrict__ h,
           __nv_bfloat16* __restrict__ l, size_t n_src, size_t n_total)
{
    size_t i = (size_t)blockIdx.x * 256 + threadIdx.x;
    if (i >= n_total) return;
    float x = (i < n_src) ? src[i] : 0.0f;
    __nv_bfloat16 hi = __float2bfloat16(x);
    h[i] = hi;
    l[i] = __float2bfloat16(x - __bfloat162float(hi));
}

// ---------------- FFMA GEMM for diag (small: 0.5 GF) ----------------
__global__ void __launch_bounds__(256, 2)
gemm_diag(const float* __restrict__ A, const float* __restrict__ Bt,
          const float* __restrict__ bias, int M, int N, int K)
{
    __shared__ float As[16][132];
    __shared__ float Bs[16][132];
    const int m0 = blockIdx.y * 128, n0 = blockIdx.x * 128;
    const int tid = threadIdx.x, tx = tid & 15, ty = tid >> 4;
    float acc[8][8];
#pragma unroll
    for (int i = 0; i < 8; i++)
#pragma unroll
        for (int j = 0; j < 8; j++) acc[i][j] = 0.0f;

    for (int k0 = 0; k0 < K; k0 += 16) {
#pragma unroll
        for (int q = 0; q < 2; q++) {
            int f4 = tid * 2 + q, row = f4 >> 2, kq = (f4 & 3) * 4;
            float4 v = *(const float4*)&A[(size_t)(m0 + row) * K + k0 + kq];
            As[kq][row] = v.x; As[kq+1][row] = v.y; As[kq+2][row] = v.z; As[kq+3][row] = v.w;
            float4 w = *(const float4*)&Bt[(size_t)(n0 + row) * K + k0 + kq];
            Bs[kq][row] = w.x; Bs[kq+1][row] = w.y; Bs[kq+2][row] = w.z; Bs[kq+3][row] = w.w;
        }
        __syncthreads();
#pragma unroll
        for (int kk = 0; kk < 16; kk++) {
            float4 a0 = *(const float4*)&As[kk][ty*8], a1 = *(const float4*)&As[kk][ty*8+4];
            float4 b0 = *(const float4*)&Bs[kk][tx*8], b1 = *(const float4*)&Bs[kk][tx*8+4];
            float a[8] = {a0.x,a0.y,a0.z,a0.w,a1.x,a1.y,a1.z,a1.w};
            float b[8] = {b0.x,b0.y,b0.z,b0.w,b1.x,b1.y,b1.z,b1.w};
#pragma unroll
            for (int i = 0; i < 8; i++)
#pragma unroll
                for (int j = 0; j < 8; j++) acc[i][j] = fmaf(a[i], b[j], acc[i][j]);
        }
        __syncthreads();
    }
#pragma unroll
    for (int i = 0; i < 8; i++) {
        int m = m0 + ty * 8 + i;
#pragma unroll
        for (int j = 0; j < 8; j++) {
            int n = n0 + tx * 8 + j;
            float x = acc[i][j] + __ldg(&bias[n]);
            x = fmaxf(x, 0.0f) + log1pf(expf(-fabsf(x))) + 1e-3f;   // softplus + min_scale
            g_diag[(size_t)m * N + n] = x;
        }
    }
}

// ---------------- sample generation -> X (bf16 hi/lo) ----------------
__global__ void __launch_bounds__(256)
gen_x(const float* __restrict__ feat, const float* __restrict__ nlr,
      const float* __restrict__ nd)
{
    __shared__ float s_lr [64][17];
    __shared__ float s_nlr[64][17];
    __shared__ float s_feat[64];
    __shared__ float s_diag[64];
    const int b = blockIdx.y, d0 = blockIdx.x * 64, tid = threadIdx.x;
    {
        int dl = tid >> 2, rq = (tid & 3) * 4;
        float4 v = *(const float4*)&g_lrcov[((size_t)b * D_ + d0 + dl) * R_ + rq];
        s_lr[dl][rq] = v.x; s_lr[dl][rq+1] = v.y; s_lr[dl][rq+2] = v.z; s_lr[dl][rq+3] = v.w;
        float4 w = *(const float4*)&nlr[((size_t)b * S_ + dl) * R_ + rq];
        s_nlr[dl][rq] = w.x; s_nlr[dl][rq+1] = w.y; s_nlr[dl][rq+2] = w.z; s_nlr[dl][rq+3] = w.w;
    }
    if (tid < 64) {
        s_feat[tid] = feat[(size_t)b * D_ + d0 + tid];
        s_diag[tid] = g_diag[(size_t)b * D_ + d0 + tid];
    }
    __syncthreads();
    for (int e = tid; e < 64 * 64; e += 256) {
        int ss = e >> 6, dl = e & 63;
        float acc = s_feat[dl];
#pragma unroll
        for (int r = 0; r < 16; r++) acc = fmaf(s_lr[dl][r], s_nlr[ss][r], acc);
        size_t idx = ((size_t)b * S_ + ss) * D_ + d0 + dl;
        acc = fmaf(s_diag[dl], nd[idx], acc);
        __nv_bfloat16 hi = __float2bfloat16(acc);
        g_Xh[idx] = hi;
        g_Xl[idx] = __float2bfloat16(acc - __bfloat162float(hi));
    }
}

extern "C" void kernel_launch(void* const* d_in, const int* in_sizes, int n_in,
                              void* d_out, int out_size)
{
    const float* features   = (const float*)d_in[0];
    const float* W_cov      = (const float*)d_in[1];
    const float* b_cov      = (const float*)d_in[2];
    const float* W_diag     = (const float*)d_in[3];
    const float* b_diag     = (const float*)d_in[4];
    const float* W_cls      = (const float*)d_in[5];
    const float* b_cls      = (const float*)d_in[6];
    const float* noise_diag = (const float*)d_in[7];
    const float* noise_lr   = (const float*)d_in[8];
    float* out = (float*)d_out;

    cudaFuncSetAttribute(mma_gemm, cudaFuncAttributeMaxDynamicSharedMemorySize, SMEM_MM);

    __nv_bfloat16 *Fh, *Fl, *Wcovh, *Wcovl, *Wch, *Wcl, *Xh, *Xl;
    cudaGetSymbolAddress((void**)&Fh, g_Fh);       cudaGetSymbolAddress((void**)&Fl, g_Fl);
    cudaGetSymbolAddress((void**)&Wcovh, g_Wcovh); cudaGetSymbolAddress((void**)&Wcovl, g_Wcovl);
    cudaGetSymbolAddress((void**)&Wch, g_Wch);     cudaGetSymbolAddress((void**)&Wcl, g_Wcl);
    cudaGetSymbolAddress((void**)&Xh, g_Xh);       cudaGetSymbolAddress((void**)&Xl, g_Xl);
    float* lrcov; cudaGetSymbolAddress((void**)&lrcov, g_lrcov);

    // splits
    split_bf16<<<(B_*D_ + 255)/256, 256>>>(features, Fh, Fl, (size_t)B_*D_, (size_t)B_*D_);
    split_bf16<<<((size_t)D_*R_*D_ + 255)/256, 256>>>(W_cov, Wcovh, Wcovl,
                                                      (size_t)D_*R_*D_, (size_t)D_*R_*D_);
    split_bf16<<<((size_t)NPAD*D_ + 255)/256, 256>>>(W_cls, Wch, Wcl,
                                                     (size_t)C_*D_, (size_t)NPAD*D_);

    // 1) lrcov = features @ W_cov^T + b_cov   (M=1024, N=8192) on tensor pipe
    mma_gemm<<<dim3(8192/128, 1024/128), 256, SMEM_MM>>>(
        Fh, Fl, Wcovh, Wcovl, b_cov, lrcov, 8192, 8192, 1.0f);

    // 2) diag_std (small, FFMA)
    gemm_diag<<<dim3(512/128, 1024/128), 256>>>(features, W_diag, b_diag, 1024, 512, 512);

    // 3) pre_logits -> Xh/Xl
    gen_x<<<dim3(D_/64, B_), 256>>>(features, noise_lr, noise_diag);

    // 4) out = (X @ W_cls^T + b_cls) / 1.5  (M=65536, N=1000 padded to 1024) on tensor pipe
    mma_gemm<<<dim3(NPAD/128, M4/128), 256, SMEM_MM>>>(
        Xh, Xl, Wch, Wcl, b_cls, out, C_, C_, 1.0f/1.5f);
}